// round 12
// baseline (speedup 1.0000x reference)
#include <cuda_runtime.h>
#include <math.h>

#define IMG_W 1024
#define IMG_H 1024
#define BATCH 8
#define CH    3
#define NPIX  (IMG_H * IMG_W)

// Scratch (static device globals — no allocation allowed)
__device__ float         g_mag[BATCH * NPIX];   // 32 MB
__device__ unsigned char g_idx[BATCH * NPIX];   //  8 MB
__device__ float         g_thin[BATCH * NPIX];  // 32 MB

// Direction offsets for dirf[d]: position of the -1 tap (dy, dx), cross-correlation
__constant__ int c_dy[8] = {0, 1, 1, 1, 0, -1, -1, -1};
__constant__ int c_dx[8] = {1, 1, 0, -1, -1, -1, 0, 1};

// ---------------- Kernel 1: blur + sobel + mag/orientation ----------------
#define TX 32
#define TY 16
#define IN_W (TX + 6)   // 38
#define IN_H (TY + 6)   // 22
#define HB_W (TX + 2)   // 34
#define BL_H (TY + 2)   // 18

// 5-tap gaussian, NEON-dot pattern: one packet of 4 products, pairwise
// predux (faddv tree: (l0+l1)+(l2+l3)), then scalar tail.
__device__ __forceinline__ float gauss5(float x0, float x1, float x2, float x3, float x4) {
    const float G0 = 0.13533528323661270f;  // f32(exp(-2))
    const float G1 = 0.60653065971263342f;  // f32(exp(-0.5))
    float p0 = __fmul_rn(G0, x0);
    float p1 = __fmul_rn(G1, x1);
    float p2 = x2;                 // w=1: exact product
    float p3 = __fmul_rn(G1, x3);
    float p4 = __fmul_rn(G0, x4);  // scalar tail
    return __fadd_rn(__fadd_rn(__fadd_rn(p0, p1), __fadd_rn(p2, p3)), p4);
}

__global__ __launch_bounds__(TX * TY) void k1_grad(const float* __restrict__ img) {
    __shared__ float s_in[IN_H][IN_W + 1];
    __shared__ float s_h [IN_H][HB_W + 1];
    __shared__ float s_b [BL_H][HB_W + 1];

    const int b  = blockIdx.z;
    const int x0 = blockIdx.x * TX;
    const int y0 = blockIdx.y * TY;
    const int tx = threadIdx.x, ty = threadIdx.y;
    const int tid = ty * TX + tx;

    float magAcc = 0.0f, oriAcc = 0.0f;

    #pragma unroll
    for (int c = 0; c < CH; c++) {
        const float* ip = img + (size_t)(b * CH + c) * NPIX;

        // Load image tile with 3-px halo, zero outside image
        for (int i = tid; i < IN_H * IN_W; i += TX * TY) {
            int iy = i / IN_W, ix = i % IN_W;
            int gy = y0 + iy - 3, gx = x0 + ix - 3;
            float v = 0.0f;
            if (gy >= 0 && gy < IMG_H && gx >= 0 && gx < IMG_W)
                v = __ldg(ip + gy * IMG_W + gx);
            s_in[iy][ix] = v;
        }
        __syncthreads();

        // Horizontal 5-tap blur (zero-padded via halo)
        for (int i = tid; i < IN_H * HB_W; i += TX * TY) {
            int iy = i / HB_W, hx = i % HB_W;
            s_h[iy][hx] = gauss5(s_in[iy][hx], s_in[iy][hx + 1], s_in[iy][hx + 2],
                                 s_in[iy][hx + 3], s_in[iy][hx + 4]);
        }
        __syncthreads();

        // Vertical 5-tap blur; mask to 0 outside the image so the Sobel's
        // zero padding semantics are exact
        for (int i = tid; i < BL_H * HB_W; i += TX * TY) {
            int by = i / HB_W, hx = i % HB_W;
            int gy = y0 + by - 1, gx = x0 + hx - 1;
            float v = 0.0f;
            if (gy >= 0 && gy < IMG_H && gx >= 0 && gx < IMG_W)
                v = gauss5(s_h[by][hx], s_h[by + 1][hx], s_h[by + 2][hx],
                           s_h[by + 3][hx], s_h[by + 4][hx]);
            s_b[by][hx] = v;
        }
        __syncthreads();

        // Sobel: NEON-dot pattern over row-major taps k0..k8.
        // Packet pass 1: lanes = products of k0..k3; pass 2: lanes = fma of
        // k4..k7 into lanes; predux (l0+l1)+(l2+l3); scalar tail k8.
        // All weights are powers of two => products exact; only the adds round.
        float a00 = s_b[ty    ][tx], a01 = s_b[ty    ][tx + 1], a02 = s_b[ty    ][tx + 2];
        float a10 = s_b[ty + 1][tx],                            a12 = s_b[ty + 1][tx + 2];
        float a20 = s_b[ty + 2][tx], a21 = s_b[ty + 2][tx + 1], a22 = s_b[ty + 2][tx + 2];

        // sx row-major taps: [a00*1, 0, -a02, 2a10, 0, -2a12, a20*1, 0, -a22]
        //   l0 = a00(+0), l1 = 0 + (-2a12), l2 = (-a02) + a20, l3 = 2a10(+0)
        {
        }
        float gl0 = a00;
        float gl1 = __fmul_rn(-2.0f, a12);
        float gl2 = __fsub_rn(a20, a02);          // fma(1, a20, -a02)
        float gl3 = __fmul_rn(2.0f, a10);
        float gx  = __fadd_rn(__fadd_rn(__fadd_rn(gl0, gl1), __fadd_rn(gl2, gl3)),
                              __fmul_rn(-1.0f, a22));

        // sy row-major taps: [a00, 2a01, a02, 0, 0, 0, -a20, -2a21, -a22]
        //   l0 = a00(+0... lanes: p0=a00, p1=2a01, p2=a02, p3=0;
        //   pass2: l0 = 0+p0, l1 = 0+p1, l2 = (-a20)+p2, l3 = (-2a21)+p3
        float hl0 = a00;
        float hl1 = __fmul_rn(2.0f, a01);
        float hl2 = __fsub_rn(a02, a20);          // fma(-1, a20, a02)
        float hl3 = __fmul_rn(-2.0f, a21);
        float gy  = __fadd_rn(__fadd_rn(__fadd_rn(hl0, hl1), __fadd_rn(hl2, hl3)),
                              __fmul_rn(-1.0f, a22));

        // mag: separate mul, mul, add, sqrt — each op individually rounded
        float sq = __fadd_rn(__fmul_rn(gx, gx), __fmul_rn(gy, gy));
        magAcc = __fadd_rn(magAcc, __fsqrt_rn(sq));

        // libdevice atan2f (atan2 impl exonerated: zero flip delta)
        oriAcc = __fadd_rn(oriAcc, atan2f(gy, gx));

        if (c < CH - 1) __syncthreads();  // protect smem across channel iters
    }

    int y = y0 + ty, x = x0 + tx;
    int o = b * NPIX + y * IMG_W + x;
    g_mag[o] = magAcc;

    // ori_deg = sum * (180/pi) + 180  (separate mul, add)
    float ori = __fadd_rn(__fmul_rn(oriAcc, 57.295779513082323f), 180.0f);
    float q = __fdiv_rn(ori, 45.0f);
    int k = (int)rintf(q);              // round half-to-even (matches jnp.round)
    g_idx[o] = (unsigned char)(k & 7);  // Python-style mod 8 (k in [-8,16])
}

// ---------------- Kernel 2: NMS with the cross-batch gather quirk ----------
// With B == 8, the reference's flat gather means:
//   positive[b,p] = mag[idx_pos][p] - mag[idx_pos][p + off(b)]
//   negative[b,p] = mag[idx_neg][p] - mag[idx_neg][p + off(b)]
// where the DIRECTION is the batch index b and the BATCH is the orientation.
__global__ __launch_bounds__(256) void k2_nms() {
    int b = blockIdx.y;
    int t = blockIdx.x * blockDim.x + threadIdx.x;
    int y = t >> 10;          // / 1024
    int x = t & (IMG_W - 1);  // % 1024

    int base = b * NPIX;
    int d  = (int)g_idx[base + t];
    int dn = (d + 4) & 7;

    int ny = y + c_dy[b];
    int nx = x + c_dx[b];
    bool inb = (ny >= 0) && (ny < IMG_H) && (nx >= 0) && (nx < IMG_W);

    float pos = g_mag[d  * NPIX + t];
    float neg = g_mag[dn * NPIX + t];
    if (inb) {
        int nt = ny * IMG_W + nx;
        pos = __fsub_rn(pos, g_mag[d  * NPIX + nt]);
        neg = __fsub_rn(neg, g_mag[dn * NPIX + nt]);
    }
    float m = g_mag[base + t];
    g_thin[base + t] = (fminf(pos, neg) > 0.0f) ? m : 0.0f;
}

// ---------------- Kernel 3: hysteresis + border zero ----------------------
__global__ __launch_bounds__(256) void k3_hyst(float* __restrict__ out) {
    int b = blockIdx.y;
    int t = blockIdx.x * blockDim.x + threadIdx.x;
    int y = t >> 10;
    int x = t & (IMG_W - 1);

    int base = b * NPIX;
    float e = 0.0f;
    if (y > 0 && y < IMG_H - 1 && x > 0 && x < IMG_W - 1) {
        float tc = g_thin[base + t];
        if (tc > 100.0f) {
            e = 1.0f;
        } else if (tc >= 10.0f) {
            const float* p = g_thin + base + t;
            bool any =
                (p[-IMG_W - 1] > 100.0f) | (p[-IMG_W] > 100.0f) | (p[-IMG_W + 1] > 100.0f) |
                (p[-1]         > 100.0f) |                        (p[1]          > 100.0f) |
                (p[ IMG_W - 1] > 100.0f) | (p[ IMG_W] > 100.0f) | (p[ IMG_W + 1] > 100.0f);
            e = any ? 1.0f : 0.0f;
        }
    }
    out[base + t] = e;
}

// ---------------- Launch ---------------------------------------------------
extern "C" void kernel_launch(void* const* d_in, const int* in_sizes, int n_in,
                              void* d_out, int out_size) {
    const float* img = (const float*)d_in[0];
    float* out = (float*)d_out;

    dim3 b1(TX, TY), g1(IMG_W / TX, IMG_H / TY, BATCH);
    k1_grad<<<g1, b1>>>(img);

    dim3 b2(256), g2(NPIX / 256, BATCH);
    k2_nms<<<g2, b2>>>();
    k3_hyst<<<g2, b2>>>(out);
}

// round 13
// speedup vs baseline: 1.0877x; 1.0877x over previous
#include <cuda_runtime.h>
#include <math.h>

#define IMG_W 1024
#define IMG_H 1024
#define BATCH 8
#define CH    3
#define NPIX  (IMG_H * IMG_W)

// Scratch (static device globals — no allocation allowed)
__device__ float         g_mag[BATCH * NPIX];   // 32 MB
__device__ unsigned char g_idx[BATCH * NPIX];   //  8 MB

// Direction offsets for dirf[d]: position of the -1 tap (dy, dx), cross-correlation
__constant__ int c_dy[8] = {0, 1, 1, 1, 0, -1, -1, -1};
__constant__ int c_dx[8] = {1, 1, 0, -1, -1, -1, 0, 1};

// ---------------- Kernel 1: blur + sobel + mag/orientation ----------------
#define TX 32
#define TY 16
#define IN_W 38            // TX + 6
#define IN_H 22            // TY + 6
#define HB_W 34            // TX + 2
#define BL_H 18            // TY + 2
#define IN_WP 40           // padded
#define HB_WP 36           // padded

// 5-tap gaussian, NEON-dot pattern (FROZEN NUMERICS — R12 passing variant):
// packet of 4 separately-rounded products, pairwise predux (l0+l1)+(l2+l3),
// scalar tail.
__device__ __forceinline__ float gauss5(float x0, float x1, float x2, float x3, float x4) {
    const float G0 = 0.13533528323661270f;  // f32(exp(-2))
    const float G1 = 0.60653065971263342f;  // f32(exp(-0.5))
    float p0 = __fmul_rn(G0, x0);
    float p1 = __fmul_rn(G1, x1);
    float p2 = x2;                 // w=1: exact product
    float p3 = __fmul_rn(G1, x3);
    float p4 = __fmul_rn(G0, x4);  // scalar tail
    return __fadd_rn(__fadd_rn(__fadd_rn(p0, p1), __fadd_rn(p2, p3)), p4);
}

__global__ __launch_bounds__(TX * TY) void k1_grad(const float* __restrict__ img) {
    __shared__ float s_in[CH][IN_H][IN_WP];   // 10560 B
    __shared__ float s_h [CH][IN_H][HB_WP];   //  9504 B
    __shared__ float s_b [CH][BL_H][HB_WP];   //  7776 B

    const int b  = blockIdx.z;
    const int x0 = blockIdx.x * TX;
    const int y0 = blockIdx.y * TY;
    const int tx = threadIdx.x, ty = threadIdx.y;

    // Block-uniform interior test: entire 38x22 input window inside image
    const bool interior = (x0 >= 3) & (x0 + IN_W - 3 <= IMG_W) &
                          (y0 >= 3) & (y0 + IN_H - 3 <= IMG_H);

    // ---- Phase 1: load 38x22 tiles for all 3 channels (no div/mod) ----
    #pragma unroll
    for (int c = 0; c < CH; c++) {
        const float* ip = img + (size_t)(b * CH + c) * NPIX;
        if (interior) {
            const float* rp0 = ip + (y0 + ty - 3) * IMG_W + (x0 - 3);
            s_in[c][ty][tx] = __ldg(rp0 + tx);
            if (tx < IN_W - TX) s_in[c][ty][tx + TX] = __ldg(rp0 + tx + TX);
            if (ty < IN_H - TY) {
                const float* rp1 = rp0 + TY * IMG_W;
                s_in[c][ty + TY][tx] = __ldg(rp1 + tx);
                if (tx < IN_W - TX) s_in[c][ty + TY][tx + TX] = __ldg(rp1 + tx + TX);
            }
        } else {
            #pragma unroll
            for (int d2 = 0; d2 < 2; d2++) {
                int iy = ty + d2 * TY;
                if (iy < IN_H) {
                    int gy = y0 + iy - 3;
                    #pragma unroll
                    for (int d1 = 0; d1 < 2; d1++) {
                        int ix = tx + d1 * TX;
                        if (ix < IN_W) {
                            int gx = x0 + ix - 3;
                            float v = 0.0f;
                            if ((unsigned)gy < IMG_H && (unsigned)gx < IMG_W)
                                v = __ldg(ip + gy * IMG_W + gx);
                            s_in[c][iy][ix] = v;
                        }
                    }
                }
            }
        }
    }
    __syncthreads();

    // ---- Phase 2: horizontal blur, 22 rows x 34 cols per channel ----
    #pragma unroll
    for (int c = 0; c < CH; c++) {
        {
            const float* r = s_in[c][ty];
            s_h[c][ty][tx] = gauss5(r[tx], r[tx+1], r[tx+2], r[tx+3], r[tx+4]);
            if (tx < HB_W - TX) {
                int hx = tx + TX;
                s_h[c][ty][hx] = gauss5(r[hx], r[hx+1], r[hx+2], r[hx+3], r[hx+4]);
            }
        }
        if (ty < IN_H - TY) {
            const float* r = s_in[c][ty + TY];
            s_h[c][ty+TY][tx] = gauss5(r[tx], r[tx+1], r[tx+2], r[tx+3], r[tx+4]);
            if (tx < HB_W - TX) {
                int hx = tx + TX;
                s_h[c][ty+TY][hx] = gauss5(r[hx], r[hx+1], r[hx+2], r[hx+3], r[hx+4]);
            }
        }
    }
    __syncthreads();

    // ---- Phase 3: vertical blur (masked to 0 outside image), 18x34 ----
    #pragma unroll
    for (int c = 0; c < CH; c++) {
        #pragma unroll
        for (int d2 = 0; d2 < 2; d2++) {
            int by = ty + d2 * TY;
            if (by < BL_H) {
                #pragma unroll
                for (int d1 = 0; d1 < 2; d1++) {
                    int hx = tx + d1 * TX;
                    if (hx < HB_W) {
                        float v;
                        if (interior) {
                            v = gauss5(s_h[c][by][hx], s_h[c][by+1][hx], s_h[c][by+2][hx],
                                       s_h[c][by+3][hx], s_h[c][by+4][hx]);
                        } else {
                            int gy = y0 + by - 1, gx = x0 + hx - 1;
                            v = 0.0f;
                            if ((unsigned)gy < IMG_H && (unsigned)gx < IMG_W)
                                v = gauss5(s_h[c][by][hx], s_h[c][by+1][hx], s_h[c][by+2][hx],
                                           s_h[c][by+3][hx], s_h[c][by+4][hx]);
                        }
                        s_b[c][by][hx] = v;
                    }
                }
            }
        }
    }
    __syncthreads();

    // ---- Phase 4: Sobel (NEON-dot, FROZEN) + mag/ori reduce ----
    float magAcc = 0.0f, oriAcc = 0.0f;
    #pragma unroll
    for (int c = 0; c < CH; c++) {
        float a00 = s_b[c][ty  ][tx], a01 = s_b[c][ty  ][tx+1], a02 = s_b[c][ty  ][tx+2];
        float a10 = s_b[c][ty+1][tx],                           a12 = s_b[c][ty+1][tx+2];
        float a20 = s_b[c][ty+2][tx], a21 = s_b[c][ty+2][tx+1], a22 = s_b[c][ty+2][tx+2];

        // sx: lanes l0=a00, l1=-2a12, l2=a20-a02, l3=2a10; predux; tail -a22
        float gl0 = a00;
        float gl1 = __fmul_rn(-2.0f, a12);
        float gl2 = __fsub_rn(a20, a02);
        float gl3 = __fmul_rn(2.0f, a10);
        float gx  = __fadd_rn(__fadd_rn(__fadd_rn(gl0, gl1), __fadd_rn(gl2, gl3)),
                              __fmul_rn(-1.0f, a22));

        // sy: lanes l0=a00, l1=2a01, l2=a02-a20, l3=-2a21; predux; tail -a22
        float hl0 = a00;
        float hl1 = __fmul_rn(2.0f, a01);
        float hl2 = __fsub_rn(a02, a20);
        float hl3 = __fmul_rn(-2.0f, a21);
        float gy  = __fadd_rn(__fadd_rn(__fadd_rn(hl0, hl1), __fadd_rn(hl2, hl3)),
                              __fmul_rn(-1.0f, a22));

        float sq = __fadd_rn(__fmul_rn(gx, gx), __fmul_rn(gy, gy));
        magAcc = __fadd_rn(magAcc, __fsqrt_rn(sq));
        oriAcc = __fadd_rn(oriAcc, atan2f(gy, gx));
    }

    int y = y0 + ty, x = x0 + tx;
    int o = b * NPIX + y * IMG_W + x;
    g_mag[o] = magAcc;

    float ori = __fadd_rn(__fmul_rn(oriAcc, 57.295779513082323f), 180.0f);
    float q = __fdiv_rn(ori, 45.0f);
    int k = (int)rintf(q);              // round half-to-even (matches jnp.round)
    g_idx[o] = (unsigned char)(k & 7);  // Python-style mod 8
}

// ------------- Kernel 2+3 fused: NMS (cross-batch gather) + hysteresis -----
// thin computed for the 34x18 halo tile into smem, then 3x3 hysteresis from
// smem. g_thin global buffer eliminated (saves ~96 MB of DRAM traffic).
__global__ __launch_bounds__(TX * TY) void k23(float* __restrict__ out) {
    __shared__ float s_t[BL_H][HB_WP];   // rows y0-1..y0+16, cols x0-1..x0+32

    const int b  = blockIdx.z;
    const int x0 = blockIdx.x * TX;
    const int y0 = blockIdx.y * TY;
    const int tx = threadIdx.x, ty = threadIdx.y;
    const int tid = ty * TX + tx;
    const int base = b * NPIX;
    const int ddy = c_dy[b], ddx = c_dx[b];

    for (int i = tid; i < BL_H * HB_W; i += TX * TY) {
        int r  = i / HB_W;
        int cc = i - r * HB_W;
        int y = y0 + r - 1, x = x0 + cc - 1;
        float tv = 0.0f;
        if ((unsigned)y < IMG_H && (unsigned)x < IMG_W) {
            int t  = y * IMG_W + x;
            int d  = (int)__ldg(&g_idx[base + t]);
            int dn = (d + 4) & 7;
            float pos = __ldg(&g_mag[d  * NPIX + t]);
            float neg = __ldg(&g_mag[dn * NPIX + t]);
            int ny = y + ddy, nx = x + ddx;
            if ((unsigned)ny < IMG_H && (unsigned)nx < IMG_W) {
                int nt = ny * IMG_W + nx;
                pos = __fsub_rn(pos, __ldg(&g_mag[d  * NPIX + nt]));
                neg = __fsub_rn(neg, __ldg(&g_mag[dn * NPIX + nt]));
            }
            if (fminf(pos, neg) > 0.0f) tv = __ldg(&g_mag[base + t]);
        }
        s_t[r][cc] = tv;
    }
    __syncthreads();

    int y = y0 + ty, x = x0 + tx;
    float e = 0.0f;
    if (y > 0 && y < IMG_H - 1 && x > 0 && x < IMG_W - 1) {
        float tc = s_t[ty + 1][tx + 1];
        if (tc > 100.0f) {
            e = 1.0f;
        } else if (tc >= 10.0f) {
            bool any =
                (s_t[ty    ][tx] > 100.0f) | (s_t[ty    ][tx+1] > 100.0f) | (s_t[ty    ][tx+2] > 100.0f) |
                (s_t[ty + 1][tx] > 100.0f) |                               (s_t[ty + 1][tx+2] > 100.0f) |
                (s_t[ty + 2][tx] > 100.0f) | (s_t[ty + 2][tx+1] > 100.0f) | (s_t[ty + 2][tx+2] > 100.0f);
            e = any ? 1.0f : 0.0f;
        }
    }
    out[base + y * IMG_W + x] = e;
}

// ---------------- Launch ---------------------------------------------------
extern "C" void kernel_launch(void* const* d_in, const int* in_sizes, int n_in,
                              void* d_out, int out_size) {
    const float* img = (const float*)d_in[0];
    float* out = (float*)d_out;

    dim3 blk(TX, TY), grd(IMG_W / TX, IMG_H / TY, BATCH);
    k1_grad<<<grd, blk>>>(img);
    k23<<<grd, blk>>>(out);
}